// round 5
// baseline (speedup 1.0000x reference)
#include <cuda_runtime.h>
#include <cuda_bf16.h>
#include <cstdint>

#define C_DIM   128
#define N_COMP  16
#define BM      128
#define THREADS 512

// smem byte map (192KB):
//   buf0: Xh @ 0,      Xl @ 32768
//   buf1: Xh @ 65536,  Xl @ 98304
//   Wh @ 131072, Wl @ 163840
#define XBUF(phase)  ((uint32_t)(phase) << 16)
#define OFF_XL  32768
#define OFF_WH  131072u
#define OFF_WL  163840u
#define HALF_BYTES 16384   // one k-half of a 128-row tile (128 rows * 128B)

__device__ __forceinline__ uint32_t smem_u32(const void* p) {
    uint32_t a;
    asm("{ .reg .u64 t; cvta.to.shared.u64 t, %1; cvt.u32.u64 %0, t; }"
        : "=r"(a) : "l"(p));
    return a;
}

__device__ __forceinline__ void ldmx4(uint32_t& r0, uint32_t& r1,
                                      uint32_t& r2, uint32_t& r3, uint32_t addr) {
    asm volatile("ldmatrix.sync.aligned.m8n8.x4.shared.b16 {%0,%1,%2,%3}, [%4];"
                 : "=r"(r0), "=r"(r1), "=r"(r2), "=r"(r3) : "r"(addr));
}

__device__ __forceinline__ void mma16816(float* c, const uint32_t* a,
                                         uint32_t b0, uint32_t b1) {
    asm volatile(
        "mma.sync.aligned.m16n8k16.row.col.f32.bf16.bf16.f32 "
        "{%0,%1,%2,%3}, {%4,%5,%6,%7}, {%8,%9}, {%0,%1,%2,%3};"
        : "+f"(c[0]), "+f"(c[1]), "+f"(c[2]), "+f"(c[3])
        : "r"(a[0]), "r"(a[1]), "r"(a[2]), "r"(a[3]), "r"(b0), "r"(b1));
}

// swizzled byte offset within one 32KB tile: two 16KB k-halves of 128B rows,
// 16B chunks XOR-permuted by (row & 7).
__device__ __forceinline__ uint32_t swz_off(int row, int k) {
    return ((uint32_t)(k >> 6) << 14) + ((uint32_t)row << 7)
         + ((uint32_t)((((k & 63) >> 3) ^ (row & 7))) << 4)
         + (uint32_t)((k & 7) << 1);
}

// Persistent kernel: one l per CTA, W[l]*pw hi/lo staged once; tile loop with
// double-buffered X and load+convert of tile t+1 interleaved into MMA of t.
__global__ __launch_bounds__(THREADS, 1)
void tp_persist2(const float* __restrict__ x,
                 const float* __restrict__ w,
                 const float* __restrict__ pw,
                 float* __restrict__ out,
                 int n_nodes, int4 gcum, int4 gsz4)
{
    extern __shared__ __align__(128) char smem[];
    const uint32_t sb = smem_u32(smem);

    const int tid  = threadIdx.x;
    const int lane = tid & 31;
    const int warp = tid >> 5;

    int bid = blockIdx.x, l, rank, gsz;
    if (bid < gcum.y)      { l = 0; rank = bid - gcum.x; gsz = gsz4.x; }
    else if (bid < gcum.z) { l = 1; rank = bid - gcum.y; gsz = gsz4.y; }
    else if (bid < gcum.w) { l = 2; rank = bid - gcum.z; gsz = gsz4.z; }
    else                   { l = 3; rank = bid - gcum.w; gsz = gsz4.w; }
    const int cl     = 2 * l + 1;
    const int mbase  = l * l;
    const int rows_l = n_nodes * cl;
    const int t_l    = (rows_l + BM - 1) / BM;

    // ---- stage W[l]*pw -> bf16 hi/lo, B layout [n][k], swizzled (once) ----
    {
        const float scale = __ldg(&pw[l]);
        const float* wp = w + (size_t)l * C_DIM * C_DIM;
        #pragma unroll
        for (int e = tid; e < C_DIM * C_DIM; e += THREADS) {
            int k = e >> 7, n = e & 127;
            float v = wp[e] * scale;
            __nv_bfloat16 h  = __float2bfloat16(v);
            __nv_bfloat16 lo = __float2bfloat16(v - __bfloat162float(h));
            uint32_t off = swz_off(n, k);
            *(__nv_bfloat16*)(smem + OFF_WH + off) = h;
            *(__nv_bfloat16*)(smem + OFF_WL + off) = lo;
        }
    }

    if (rank >= t_l) return;

    const float4* x4 = (const float4*)x;
    const int my_lr = tid >> 5;   // this thread's row-within-chunk base is chunk*16 + (tid>>5)
    const int my_v  = tid & 31;   // float4 column index (cols 4v..4v+3)

    // LDG one chunk (16 rows) of tile 'tl' (chunk in [0,8))
    auto ldg_chunk = [&](int tl, int chunk) -> float4 {
        int lr = chunk * 16 + my_lr;
        int r  = tl * BM + lr;
        float4 f = make_float4(0.f, 0.f, 0.f, 0.f);
        if (r < rows_l) {
            int node = r / cl;
            int m    = mbase + (r - node * cl);
            f = __ldg(x4 + ((size_t)node * N_COMP + m) * 32 + my_v);
        }
        return f;
    };

    // convert float4 -> bf16 hi/lo and store into buffer 'nb' at chunk
    auto cvt_store = [&](float4 f, uint32_t nb, int chunk) {
        int lr = chunk * 16 + my_lr;
        __nv_bfloat162 h0 = __floats2bfloat162_rn(f.x, f.y);
        __nv_bfloat162 h1 = __floats2bfloat162_rn(f.z, f.w);
        __nv_bfloat162 l0 = __floats2bfloat162_rn(
            f.x - __bfloat162float(__low2bfloat16(h0)),
            f.y - __bfloat162float(__high2bfloat16(h0)));
        __nv_bfloat162 l1 = __floats2bfloat162_rn(
            f.z - __bfloat162float(__low2bfloat16(h1)),
            f.w - __bfloat162float(__high2bfloat16(h1)));
        uint32_t off = swz_off(lr, my_v * 4);
        uint2 uh, ul;
        uh.x = *(uint32_t*)&h0; uh.y = *(uint32_t*)&h1;
        ul.x = *(uint32_t*)&l0; ul.y = *(uint32_t*)&l1;
        *(uint2*)(smem + nb + off)          = uh;
        *(uint2*)(smem + nb + OFF_XL + off) = ul;
    };

    // ---- fragment addressing (swizzle-aware) ----
    const int wr = warp & 3;
    const int wc = warp >> 2;
    const int a_hi = lane >> 4;
    int a_row[2], a_s[2];
    #pragma unroll
    for (int mt = 0; mt < 2; mt++) {
        a_row[mt] = wr * 32 + mt * 16 + (lane & 15);
        a_s[mt]   = a_row[mt] & 7;
    }
    const int bg   = lane >> 3;
    const int b_hi = bg & 1;
    int b_row[2], b_s[2];
    #pragma unroll
    for (int nt = 0; nt < 2; nt++) {
        b_row[nt] = wc * 32 + nt * 16 + ((bg >> 1) * 8) + (lane & 7);
        b_s[nt]   = b_row[nt] & 7;
    }
    const int grp = lane >> 2;
    const int qid = lane & 3;

    // ---- prologue: convert first tile into buffer 0 ----
    {
        #pragma unroll
        for (int c = 0; c < 8; c++) {
            float4 f = ldg_chunk(rank, c);
            cvt_store(f, XBUF(0), c);
        }
    }
    __syncthreads();

    int phase = 0;
    for (int tl = rank; tl < t_l; tl += gsz) {
        const int row0 = tl * BM;
        const int nxt = tl + gsz;
        const bool has_next = (nxt < t_l);
        const uint32_t xb = sb + XBUF(phase);
        const uint32_t nb = XBUF(phase ^ 1);

        float acc[2][4][4];
        #pragma unroll
        for (int mt = 0; mt < 2; mt++)
            #pragma unroll
            for (int n8 = 0; n8 < 4; n8++)
                #pragma unroll
                for (int j = 0; j < 4; j++) acc[mt][n8][j] = 0.f;

        float4 pend;
        if (has_next) pend = ldg_chunk(nxt, 0);

        #pragma unroll
        for (int ks = 0; ks < 8; ks++) {
            const uint32_t hoff = (ks & 4) ? HALF_BYTES : 0u;
            const int c0 = (ks & 3) * 2;

            uint32_t Ah[2][4], Al[2][4];
            #pragma unroll
            for (int mt = 0; mt < 2; mt++) {
                uint32_t a = xb + hoff + (uint32_t)(a_row[mt] << 7)
                           + (uint32_t)((((c0 | a_hi) ^ a_s[mt])) << 4);
                ldmx4(Ah[mt][0], Ah[mt][1], Ah[mt][2], Ah[mt][3], a);
                ldmx4(Al[mt][0], Al[mt][1], Al[mt][2], Al[mt][3], a + OFF_XL);
            }
            uint32_t Bh[2][4], Bl[2][4];
            #pragma unroll
            for (int nt = 0; nt < 2; nt++) {
                uint32_t b = sb + hoff + (uint32_t)(b_row[nt] << 7)
                           + (uint32_t)((((c0 | b_hi) ^ b_s[nt])) << 4);
                ldmx4(Bh[nt][0], Bh[nt][1], Bh[nt][2], Bh[nt][3], b + OFF_WH);
                ldmx4(Bl[nt][0], Bl[nt][1], Bl[nt][2], Bl[nt][3], b + OFF_WL);
            }
            #pragma unroll
            for (int mt = 0; mt < 2; mt++)
                #pragma unroll
                for (int n8 = 0; n8 < 4; n8++) {
                    const int nt = n8 >> 1, p = (n8 & 1) * 2;
                    mma16816(acc[mt][n8], Ah[mt], Bh[nt][p], Bh[nt][p + 1]);
                    mma16816(acc[mt][n8], Al[mt], Bh[nt][p], Bh[nt][p + 1]);
                    mma16816(acc[mt][n8], Ah[mt], Bl[nt][p], Bl[nt][p + 1]);
                }

            // interleaved producer work for tile t+1 (other buffer, no sync)
            if (has_next) {
                cvt_store(pend, nb, ks);
                if (ks < 7) pend = ldg_chunk(nxt, ks + 1);
            }
        }

        // ---- epilogue: fire-and-forget STGs, then one sync ----
        #pragma unroll
        for (int mt = 0; mt < 2; mt++) {
            #pragma unroll
            for (int h = 0; h < 2; h++) {
                int r = row0 + wr * 32 + mt * 16 + grp + h * 8;
                if (r < rows_l) {
                    int node = r / cl;
                    int m    = mbase + (r - node * cl);
                    float* orow = out + ((size_t)node * N_COMP + m) * C_DIM
                                      + wc * 32 + qid * 2;
                    #pragma unroll
                    for (int n8 = 0; n8 < 4; n8++) {
                        float2 v2 = make_float2(acc[mt][n8][h * 2],
                                                acc[mt][n8][h * 2 + 1]);
                        *(float2*)(orow + n8 * 8) = v2;
                    }
                }
            }
        }
        __syncthreads();
        phase ^= 1;
    }
}

extern "C" void kernel_launch(void* const* d_in, const int* in_sizes, int n_in,
                              void* d_out, int out_size) {
    const float* x  = (const float*)d_in[0];
    const float* w  = (const float*)d_in[1];
    const float* pw = (const float*)d_in[2];
    float* out = (float*)d_out;

    const int n_nodes = in_sizes[0] / (N_COMP * C_DIM);

    int dev = 0, nsm = 148;
    cudaGetDevice(&dev);
    cudaDeviceGetAttribute(&nsm, cudaDevAttrMultiProcessorCount, dev);

    long long t[4], T = 0;
    for (int l = 0; l < 4; l++) {
        t[l] = ((long long)n_nodes * (2 * l + 1) + BM - 1) / BM;
        T += t[l];
    }
    int g[4], used = 0;
    for (int l = 0; l < 3; l++) {
        g[l] = (int)(((long long)nsm * t[l]) / T);
        if (g[l] < 1) g[l] = 1;
        used += g[l];
    }
    g[3] = nsm - used;
    if (g[3] < 1) g[3] = 1;

    int4 gcum = make_int4(0, g[0], g[0] + g[1], g[0] + g[1] + g[2]);
    int4 gsz4 = make_int4(g[0], g[1], g[2], g[3]);
    int grid = g[0] + g[1] + g[2] + g[3];

    size_t smem_bytes = 196608;   // 192KB
    cudaFuncSetAttribute(tp_persist2,
                         cudaFuncAttributeMaxDynamicSharedMemorySize,
                         (int)smem_bytes);

    tp_persist2<<<grid, THREADS, smem_bytes>>>(x, w, pw, out,
                                               n_nodes, gcum, gsz4);
}

// round 6
// speedup vs baseline: 1.0938x; 1.0938x over previous
#include <cuda_runtime.h>
#include <cuda_bf16.h>
#include <cstdint>

#define C_DIM   128
#define N_COMP  16
#define BM      64
#define THREADS 256

// smem per CTA (96KB):
//   Xh @ 0      (16KB: 64 rows x 128 k bf16, two 8KB k-halves, swizzled)
//   Xl @ 16384
//   Wh @ 32768  (32KB: 128 n x 128 k bf16, two 16KB k-halves, swizzled)
//   Wl @ 65536
#define OFF_XH  0u
#define OFF_XL  16384u
#define OFF_WH  32768u
#define OFF_WL  65536u

__device__ __forceinline__ uint32_t smem_u32(const void* p) {
    uint32_t a;
    asm("{ .reg .u64 t; cvta.to.shared.u64 t, %1; cvt.u32.u64 %0, t; }"
        : "=r"(a) : "l"(p));
    return a;
}

__device__ __forceinline__ void ldmx4(uint32_t& r0, uint32_t& r1,
                                      uint32_t& r2, uint32_t& r3, uint32_t addr) {
    asm volatile("ldmatrix.sync.aligned.m8n8.x4.shared.b16 {%0,%1,%2,%3}, [%4];"
                 : "=r"(r0), "=r"(r1), "=r"(r2), "=r"(r3) : "r"(addr));
}

__device__ __forceinline__ void mma16816(float* c, const uint32_t* a,
                                         uint32_t b0, uint32_t b1) {
    asm volatile(
        "mma.sync.aligned.m16n8k16.row.col.f32.bf16.bf16.f32 "
        "{%0,%1,%2,%3}, {%4,%5,%6,%7}, {%8,%9}, {%0,%1,%2,%3};"
        : "+f"(c[0]), "+f"(c[1]), "+f"(c[2]), "+f"(c[3])
        : "r"(a[0]), "r"(a[1]), "r"(a[2]), "r"(a[3]), "r"(b0), "r"(b1));
}

// swizzled byte offset, X tile (64 rows): k-halves of 8KB
__device__ __forceinline__ uint32_t swz_x(int row, int k) {
    return ((uint32_t)(k >> 6) << 13) + ((uint32_t)row << 7)
         + ((uint32_t)((((k & 63) >> 3) ^ (row & 7))) << 4)
         + (uint32_t)((k & 7) << 1);
}
// swizzled byte offset, W tile (128 rows): k-halves of 16KB
__device__ __forceinline__ uint32_t swz_w(int row, int k) {
    return ((uint32_t)(k >> 6) << 14) + ((uint32_t)row << 7)
         + ((uint32_t)((((k & 63) >> 3) ^ (row & 7))) << 4)
         + (uint32_t)((k & 7) << 1);
}

// Persistent kernel, 2 CTAs/SM. Each CTA: one l, W[l]*pw hi/lo staged once,
// then loops 64-row tiles: bulk LDG -> convert -> MMA -> STG.
// Cross-CTA phase overlap keeps the tensor pipe fed.
__global__ __launch_bounds__(THREADS, 2)
void tp_persist3(const float* __restrict__ x,
                 const float* __restrict__ w,
                 const float* __restrict__ pw,
                 float* __restrict__ out,
                 int n_nodes, int4 gcum, int4 gsz4)
{
    extern __shared__ __align__(128) char smem[];
    const uint32_t sb = smem_u32(smem);

    const int tid  = threadIdx.x;
    const int lane = tid & 31;
    const int warp = tid >> 5;

    int bid = blockIdx.x, l, rank, gsz;
    if (bid < gcum.y)      { l = 0; rank = bid - gcum.x; gsz = gsz4.x; }
    else if (bid < gcum.z) { l = 1; rank = bid - gcum.y; gsz = gsz4.y; }
    else if (bid < gcum.w) { l = 2; rank = bid - gcum.z; gsz = gsz4.z; }
    else                   { l = 3; rank = bid - gcum.w; gsz = gsz4.w; }
    const int cl     = 2 * l + 1;
    const int mbase  = l * l;
    const int rows_l = n_nodes * cl;
    const int t_l    = (rows_l + BM - 1) / BM;

    // ---- stage W[l]*pw -> bf16 hi/lo (once per CTA) ----
    {
        const float scale = __ldg(&pw[l]);
        const float* wp = w + (size_t)l * C_DIM * C_DIM;
        #pragma unroll
        for (int e = tid; e < C_DIM * C_DIM; e += THREADS) {
            int k = e >> 7, n = e & 127;
            float v = wp[e] * scale;
            __nv_bfloat16 h  = __float2bfloat16(v);
            __nv_bfloat16 lo = __float2bfloat16(v - __bfloat162float(h));
            uint32_t off = swz_w(n, k);
            *(__nv_bfloat16*)(smem + OFF_WH + off) = h;
            *(__nv_bfloat16*)(smem + OFF_WL + off) = lo;
        }
    }

    if (rank >= t_l) return;

    const float4* x4 = (const float4*)x;
    const int my_lr = tid >> 5;   // row within 8-row group
    const int my_v  = tid & 31;   // float4 column

    // ---- fragment addressing (warp tile 32x32: 2 row-blocks x 4 col-blocks) ----
    const int wr = warp & 1;
    const int wc = warp >> 1;
    const int a_hi = lane >> 4;
    int a_row[2], a_s[2];
    #pragma unroll
    for (int mt = 0; mt < 2; mt++) {
        a_row[mt] = wr * 32 + mt * 16 + (lane & 15);
        a_s[mt]   = a_row[mt] & 7;
    }
    const int bg   = lane >> 3;
    const int b_hi = bg & 1;
    int b_row[2], b_s[2];
    #pragma unroll
    for (int nt = 0; nt < 2; nt++) {
        b_row[nt] = wc * 32 + nt * 16 + ((bg >> 1) * 8) + (lane & 7);
        b_s[nt]   = b_row[nt] & 7;
    }
    const int grp = lane >> 2;
    const int qid = lane & 3;

    __syncthreads();   // W visible before first MMA phase

    for (int tl = rank; tl < t_l; tl += gsz) {
        const int row0 = tl * BM;

        // ---- bulk load: 8 independent LDG.128 per thread (MLP=8) ----
        float4 v[8];
        #pragma unroll
        for (int c = 0; c < 8; c++) {
            int lr = c * 8 + my_lr;          // 8 chunks x 8 rows = 64 rows
            int r  = row0 + lr;
            v[c] = make_float4(0.f, 0.f, 0.f, 0.f);
            if (r < rows_l) {
                int node = r / cl;
                int m    = mbase + (r - node * cl);
                v[c] = __ldg(x4 + ((size_t)node * N_COMP + m) * 32 + my_v);
            }
        }

        // ---- convert -> Xh/Xl (swizzled) ----
        #pragma unroll
        for (int c = 0; c < 8; c++) {
            int lr = c * 8 + my_lr;
            float4 f = v[c];
            __nv_bfloat162 h0 = __floats2bfloat162_rn(f.x, f.y);
            __nv_bfloat162 h1 = __floats2bfloat162_rn(f.z, f.w);
            __nv_bfloat162 l0 = __floats2bfloat162_rn(
                f.x - __bfloat162float(__low2bfloat16(h0)),
                f.y - __bfloat162float(__high2bfloat16(h0)));
            __nv_bfloat162 l1 = __floats2bfloat162_rn(
                f.z - __bfloat162float(__low2bfloat16(h1)),
                f.w - __bfloat162float(__high2bfloat16(h1)));
            uint32_t off = swz_x(lr, my_v * 4);
            uint2 uh, ul;
            uh.x = *(uint32_t*)&h0; uh.y = *(uint32_t*)&h1;
            ul.x = *(uint32_t*)&l0; ul.y = *(uint32_t*)&l1;
            *(uint2*)(smem + OFF_XH + off) = uh;
            *(uint2*)(smem + OFF_XL + off) = ul;
        }
        __syncthreads();

        // ---- fused 3-product mainloop over 8 k16-steps ----
        float acc[2][4][4];
        #pragma unroll
        for (int mt = 0; mt < 2; mt++)
            #pragma unroll
            for (int n8 = 0; n8 < 4; n8++)
                #pragma unroll
                for (int j = 0; j < 4; j++) acc[mt][n8][j] = 0.f;

        #pragma unroll
        for (int ks = 0; ks < 8; ks++) {
            const uint32_t xoff = (ks & 4) ? 8192u : 0u;
            const uint32_t woff = (ks & 4) ? 16384u : 0u;
            const int c0 = (ks & 3) * 2;

            uint32_t Ah[2][4], Al[2][4];
            #pragma unroll
            for (int mt = 0; mt < 2; mt++) {
                uint32_t a = sb + xoff + (uint32_t)(a_row[mt] << 7)
                           + (uint32_t)((((c0 | a_hi) ^ a_s[mt])) << 4);
                ldmx4(Ah[mt][0], Ah[mt][1], Ah[mt][2], Ah[mt][3], a + OFF_XH);
                ldmx4(Al[mt][0], Al[mt][1], Al[mt][2], Al[mt][3], a + OFF_XL);
            }
            uint32_t Bh[2][4], Bl[2][4];
            #pragma unroll
            for (int nt = 0; nt < 2; nt++) {
                uint32_t b = sb + woff + (uint32_t)(b_row[nt] << 7)
                           + (uint32_t)((((c0 | b_hi) ^ b_s[nt])) << 4);
                ldmx4(Bh[nt][0], Bh[nt][1], Bh[nt][2], Bh[nt][3], b + OFF_WH);
                ldmx4(Bl[nt][0], Bl[nt][1], Bl[nt][2], Bl[nt][3], b + OFF_WL);
            }
            #pragma unroll
            for (int mt = 0; mt < 2; mt++)
                #pragma unroll
                for (int n8 = 0; n8 < 4; n8++) {
                    const int nt = n8 >> 1, p = (n8 & 1) * 2;
                    mma16816(acc[mt][n8], Ah[mt], Bh[nt][p], Bh[nt][p + 1]);
                    mma16816(acc[mt][n8], Al[mt], Bh[nt][p], Bh[nt][p + 1]);
                    mma16816(acc[mt][n8], Ah[mt], Bl[nt][p], Bl[nt][p + 1]);
                }
        }

        // ---- epilogue: STG, then sync before next tile overwrites X ----
        #pragma unroll
        for (int mt = 0; mt < 2; mt++) {
            #pragma unroll
            for (int h = 0; h < 2; h++) {
                int r = row0 + wr * 32 + mt * 16 + grp + h * 8;
                if (r < rows_l) {
                    int node = r / cl;
                    int m    = mbase + (r - node * cl);
                    float* orow = out + ((size_t)node * N_COMP + m) * C_DIM
                                      + wc * 32 + qid * 2;
                    #pragma unroll
                    for (int n8 = 0; n8 < 4; n8++) {
                        float2 v2 = make_float2(acc[mt][n8][h * 2],
                                                acc[mt][n8][h * 2 + 1]);
                        *(float2*)(orow + n8 * 8) = v2;
                    }
                }
            }
        }
        __syncthreads();
    }
}

extern "C" void kernel_launch(void* const* d_in, const int* in_sizes, int n_in,
                              void* d_out, int out_size) {
    const float* x  = (const float*)d_in[0];
    const float* w  = (const float*)d_in[1];
    const float* pw = (const float*)d_in[2];
    float* out = (float*)d_out;

    const int n_nodes = in_sizes[0] / (N_COMP * C_DIM);

    int dev = 0, nsm = 148;
    cudaGetDevice(&dev);
    cudaDeviceGetAttribute(&nsm, cudaDevAttrMultiProcessorCount, dev);
    const int nw = 2 * nsm;   // 2 CTAs per SM

    long long t[4], T = 0;
    for (int l = 0; l < 4; l++) {
        t[l] = ((long long)n_nodes * (2 * l + 1) + BM - 1) / BM;
        T += t[l];
    }
    int g[4], used = 0;
    for (int l = 0; l < 3; l++) {
        g[l] = (int)(((long long)nw * t[l]) / T);
        if (g[l] < 1) g[l] = 1;
        used += g[l];
    }
    g[3] = nw - used;
    if (g[3] < 1) g[3] = 1;

    int4 gcum = make_int4(0, g[0], g[0] + g[1], g[0] + g[1] + g[2]);
    int4 gsz4 = make_int4(g[0], g[1], g[2], g[3]);
    int grid = g[0] + g[1] + g[2] + g[3];

    size_t smem_bytes = 98304;   // 96KB per CTA -> 2 CTAs/SM
    cudaFuncSetAttribute(tp_persist3,
                         cudaFuncAttributeMaxDynamicSharedMemorySize,
                         (int)smem_bytes);

    tp_persist3<<<grid, THREADS, smem_bytes>>>(x, w, pw, out,
                                               n_nodes, gcum, gsz4);
}

// round 7
// speedup vs baseline: 1.2227x; 1.1179x over previous
#include <cuda_runtime.h>
#include <cuda_bf16.h>
#include <cstdint>

#define C_DIM   128
#define N_COMP  16
#define BM      128
#define THREADS 512

// smem (192KB):
//   X buf0: Xh @ 0      Xl @ 32768
//   X buf1: Xh @ 65536  Xl @ 98304
//   Wh @ 131072, Wl @ 163840
#define XBUF(p)  ((uint32_t)(p) << 16)
#define OFF_XL   32768u
#define OFF_WH   131072u
#define OFF_WL   163840u
#define HALF     16384u      // one k-half of a 128-row tile

__device__ __forceinline__ uint32_t smem_u32(const void* p) {
    uint32_t a;
    asm("{ .reg .u64 t; cvta.to.shared.u64 t, %1; cvt.u32.u64 %0, t; }"
        : "=r"(a) : "l"(p));
    return a;
}
__device__ __forceinline__ void bar_sync(int id) {
    asm volatile("bar.sync %0, 512;" :: "r"(id) : "memory");
}
__device__ __forceinline__ void bar_arrive(int id) {
    asm volatile("bar.arrive %0, 512;" :: "r"(id) : "memory");
}
__device__ __forceinline__ void ldmx4(uint32_t& r0, uint32_t& r1,
                                      uint32_t& r2, uint32_t& r3, uint32_t addr) {
    asm volatile("ldmatrix.sync.aligned.m8n8.x4.shared.b16 {%0,%1,%2,%3}, [%4];"
                 : "=r"(r0), "=r"(r1), "=r"(r2), "=r"(r3) : "r"(addr));
}
__device__ __forceinline__ void mma16816(float* c, const uint32_t* a,
                                         uint32_t b0, uint32_t b1) {
    asm volatile(
        "mma.sync.aligned.m16n8k16.row.col.f32.bf16.bf16.f32 "
        "{%0,%1,%2,%3}, {%4,%5,%6,%7}, {%8,%9}, {%0,%1,%2,%3};"
        : "+f"(c[0]), "+f"(c[1]), "+f"(c[2]), "+f"(c[3])
        : "r"(a[0]), "r"(a[1]), "r"(a[2]), "r"(a[3]), "r"(b0), "r"(b1));
}

// swizzled byte offset within a 128-row x 128-k bf16 tile (two 16KB k-halves,
// 128B rows, 16B chunks XOR-permuted by row&7)
__device__ __forceinline__ uint32_t swz_off(int row, int k) {
    return ((uint32_t)(k >> 6) << 14) + ((uint32_t)row << 7)
         + ((uint32_t)((((k & 63) >> 3) ^ (row & 7))) << 4)
         + (uint32_t)((k & 7) << 1);
}

// Warp-specialized persistent kernel: warps 0-7 consume (MMA+STG),
// warps 8-15 produce (LDG + bf16 hi/lo split + STS). Double-buffered X.
__global__ __launch_bounds__(THREADS, 1)
void tp_ws(const float* __restrict__ x,
           const float* __restrict__ w,
           const float* __restrict__ pw,
           float* __restrict__ out,
           int n_nodes, int4 gcum, int4 gsz4)
{
    extern __shared__ __align__(128) char smem[];
    const uint32_t sb = smem_u32(smem);

    const int tid  = threadIdx.x;
    const int lane = tid & 31;
    const int warp = tid >> 5;

    int bid = blockIdx.x, l, rank, gsz;
    if (bid < gcum.y)      { l = 0; rank = bid - gcum.x; gsz = gsz4.x; }
    else if (bid < gcum.z) { l = 1; rank = bid - gcum.y; gsz = gsz4.y; }
    else if (bid < gcum.w) { l = 2; rank = bid - gcum.z; gsz = gsz4.z; }
    else                   { l = 3; rank = bid - gcum.w; gsz = gsz4.w; }
    const int cl     = 2 * l + 1;
    const int mbase  = l * l;
    const int rows_l = n_nodes * cl;
    const int t_l    = (rows_l + BM - 1) / BM;

    // ---- stage W[l]*pw -> bf16 hi/lo (all threads, once) ----
    {
        const float scale = __ldg(&pw[l]);
        const float* wp = w + (size_t)l * C_DIM * C_DIM;
        #pragma unroll
        for (int e = tid; e < C_DIM * C_DIM; e += THREADS) {
            int k = e >> 7, n = e & 127;
            float v = wp[e] * scale;
            __nv_bfloat16 h  = __float2bfloat16(v);
            __nv_bfloat16 lo = __float2bfloat16(v - __bfloat162float(h));
            uint32_t off = swz_off(n, k);
            *(__nv_bfloat16*)(smem + OFF_WH + off) = h;
            *(__nv_bfloat16*)(smem + OFF_WL + off) = lo;
        }
    }
    __syncthreads();

    if (rank >= t_l) return;   // whole CTA exits together

    if (warp >= 8) {
        // ================= PRODUCER =================
        const float4* x4 = (const float4*)x;
        const int ptid  = tid - 256;
        const int my_lr = ptid >> 5;   // 0..7
        const int my_v  = ptid & 31;

        int i = 0;
        for (int tl = rank; tl < t_l; tl += gsz, i++) {
            const int p = i & 1;
            const int row0 = tl * BM;
            const uint32_t xb = XBUF(p);

            #pragma unroll
            for (int wave = 0; wave < 2; wave++) {
                // 8 independent LDG.128 (rows wave*64 + c*8 + my_lr)
                float4 v[8];
                #pragma unroll
                for (int c = 0; c < 8; c++) {
                    int lr = wave * 64 + c * 8 + my_lr;
                    int r  = row0 + lr;
                    v[c] = make_float4(0.f, 0.f, 0.f, 0.f);
                    if (r < rows_l) {
                        int node = r / cl;
                        int m    = mbase + (r - node * cl);
                        v[c] = __ldg(x4 + ((size_t)node * N_COMP + m) * 32 + my_v);
                    }
                }
                // wait for consumer to free this buffer (only first wave)
                if (wave == 0 && i >= 2) bar_sync(3 + p);
                // convert + STS
                #pragma unroll
                for (int c = 0; c < 8; c++) {
                    int lr = wave * 64 + c * 8 + my_lr;
                    float4 f = v[c];
                    __nv_bfloat162 h0 = __floats2bfloat162_rn(f.x, f.y);
                    __nv_bfloat162 h1 = __floats2bfloat162_rn(f.z, f.w);
                    __nv_bfloat162 l0 = __floats2bfloat162_rn(
                        f.x - __bfloat162float(__low2bfloat16(h0)),
                        f.y - __bfloat162float(__high2bfloat16(h0)));
                    __nv_bfloat162 l1 = __floats2bfloat162_rn(
                        f.z - __bfloat162float(__low2bfloat16(h1)),
                        f.w - __bfloat162float(__high2bfloat16(h1)));
                    uint32_t off = xb + swz_off(lr, my_v * 4);
                    uint2 uh, ul;
                    uh.x = *(uint32_t*)&h0; uh.y = *(uint32_t*)&h1;
                    ul.x = *(uint32_t*)&l0; ul.y = *(uint32_t*)&l1;
                    *(uint2*)(smem + off)          = uh;
                    *(uint2*)(smem + OFF_XL + off) = ul;
                }
            }
            bar_arrive(1 + p);   // buffer p full
        }
    } else {
        // ================= CONSUMER =================
        const int wr = warp & 3;      // 32-row block
        const int wc = warp >> 2;     // 64-col block
        const int a_hi = lane >> 4;
        int a_row[2], a_s[2];
        #pragma unroll
        for (int mt = 0; mt < 2; mt++) {
            a_row[mt] = wr * 32 + mt * 16 + (lane & 15);
            a_s[mt]   = a_row[mt] & 7;
        }
        const int bg   = lane >> 3;
        const int b_hi = bg & 1;
        int b_row[4], b_s[4];
        #pragma unroll
        for (int nt = 0; nt < 4; nt++) {
            b_row[nt] = wc * 64 + nt * 16 + ((bg >> 1) * 8) + (lane & 7);
            b_s[nt]   = b_row[nt] & 7;
        }
        const int grp = lane >> 2;
        const int qid = lane & 3;

        int i = 0;
        for (int tl = rank; tl < t_l; tl += gsz, i++) {
            const int p = i & 1;
            const int row0 = tl * BM;
            const uint32_t xb = sb + XBUF(p);

            bar_sync(1 + p);   // wait buffer p full

            float acc[2][8][4];
            #pragma unroll
            for (int mt = 0; mt < 2; mt++)
                #pragma unroll
                for (int n8 = 0; n8 < 8; n8++)
                    #pragma unroll
                    for (int j = 0; j < 4; j++) acc[mt][n8][j] = 0.f;

            #pragma unroll
            for (int ks = 0; ks < 8; ks++) {
                const uint32_t hoff = (ks & 4) ? HALF : 0u;
                const int c0 = (ks & 3) * 2;

                uint32_t Ah[2][4], Al[2][4];
                #pragma unroll
                for (int mt = 0; mt < 2; mt++) {
                    uint32_t a = xb + hoff + (uint32_t)(a_row[mt] << 7)
                               + (uint32_t)((((c0 | a_hi) ^ a_s[mt])) << 4);
                    ldmx4(Ah[mt][0], Ah[mt][1], Ah[mt][2], Ah[mt][3], a);
                    ldmx4(Al[mt][0], Al[mt][1], Al[mt][2], Al[mt][3], a + OFF_XL);
                }
                uint32_t Bh[4][4], Bl[4][4];
                #pragma unroll
                for (int nt = 0; nt < 4; nt++) {
                    uint32_t b = sb + hoff + (uint32_t)(b_row[nt] << 7)
                               + (uint32_t)((((c0 | b_hi) ^ b_s[nt])) << 4);
                    ldmx4(Bh[nt][0], Bh[nt][1], Bh[nt][2], Bh[nt][3], b + OFF_WH);
                    ldmx4(Bl[nt][0], Bl[nt][1], Bl[nt][2], Bl[nt][3], b + OFF_WL);
                }
                #pragma unroll
                for (int mt = 0; mt < 2; mt++)
                    #pragma unroll
                    for (int n8 = 0; n8 < 8; n8++) {
                        const int nt = n8 >> 1, q = (n8 & 1) * 2;
                        mma16816(acc[mt][n8], Ah[mt], Bh[nt][q], Bh[nt][q + 1]);
                        mma16816(acc[mt][n8], Al[mt], Bh[nt][q], Bh[nt][q + 1]);
                        mma16816(acc[mt][n8], Ah[mt], Bl[nt][q], Bl[nt][q + 1]);
                    }
            }

            bar_arrive(3 + p);   // buffer p free (epilogue uses regs only)

            // ---- epilogue: STG ----
            #pragma unroll
            for (int mt = 0; mt < 2; mt++) {
                #pragma unroll
                for (int h = 0; h < 2; h++) {
                    int r = row0 + wr * 32 + mt * 16 + grp + h * 8;
                    if (r < rows_l) {
                        int node = r / cl;
                        int m    = mbase + (r - node * cl);
                        float* orow = out + ((size_t)node * N_COMP + m) * C_DIM
                                          + wc * 64 + qid * 2;
                        #pragma unroll
                        for (int n8 = 0; n8 < 8; n8++) {
                            float2 v2 = make_float2(acc[mt][n8][h * 2],
                                                    acc[mt][n8][h * 2 + 1]);
                            *(float2*)(orow + n8 * 8) = v2;
                        }
                    }
                }
            }
        }
    }
}

extern "C" void kernel_launch(void* const* d_in, const int* in_sizes, int n_in,
                              void* d_out, int out_size) {
    const float* x  = (const float*)d_in[0];
    const float* w  = (const float*)d_in[1];
    const float* pw = (const float*)d_in[2];
    float* out = (float*)d_out;

    const int n_nodes = in_sizes[0] / (N_COMP * C_DIM);

    int dev = 0, nsm = 148;
    cudaGetDevice(&dev);
    cudaDeviceGetAttribute(&nsm, cudaDevAttrMultiProcessorCount, dev);

    long long t[4], T = 0;
    for (int l = 0; l < 4; l++) {
        t[l] = ((long long)n_nodes * (2 * l + 1) + BM - 1) / BM;
        T += t[l];
    }
    int g[4], used = 0;
    for (int l = 0; l < 3; l++) {
        g[l] = (int)(((long long)nsm * t[l]) / T);
        if (g[l] < 1) g[l] = 1;
        used += g[l];
    }
    g[3] = nsm - used;
    if (g[3] < 1) g[3] = 1;

    int4 gcum = make_int4(0, g[0], g[0] + g[1], g[0] + g[1] + g[2]);
    int4 gsz4 = make_int4(g[0], g[1], g[2], g[3]);
    int grid = g[0] + g[1] + g[2] + g[3];

    size_t smem_bytes = 196608;   // 192KB
    cudaFuncSetAttribute(tp_ws,
                         cudaFuncAttributeMaxDynamicSharedMemorySize,
                         (int)smem_bytes);

    tp_ws<<<grid, THREADS, smem_bytes>>>(x, w, pw, out, n_nodes, gcum, gsz4);
}